// round 4
// baseline (speedup 1.0000x reference)
#include <cuda_runtime.h>
#include <math.h>
#include <stdint.h>

// ---------------- problem constants ----------------
#define DIMc   384
#define NHc    12
#define HDc    32
#define Bc     4
#define Tc     128
#define FRc    64
#define Lc     (Tc*FRc)        // 8192
#define BLc    (Bc*Lc)         // 32768
#define T2c    4
#define F2c    8
#define T1c    (Tc/T2c)        // 32
#define F1c    (FRc/F2c)       // 8
#define EPSc   1e-6f

// ---------------- scratch (device globals; no runtime alloc) ----------------
__device__ float g_xs [BLc*DIMc];     // token-major activations (residual stream)
__device__ float g_xn [BLc*DIMc];     // rms-normalized activations
__device__ float g_qkv[BLc*3*DIMc];   // qkv (q,k roped in place)
__device__ float g_y  [BLc*DIMc];     // attention output accumulator
__device__ float g_xs2[BLc*DIMc];     // after proj residual
__device__ float g_h  [BLc*4*DIMc];   // mlp hidden

// ---------------- transpose in: x (B,DIM,L) -> xs (B,L,DIM) ----------------
__global__ void k_transpose_in(const float* __restrict__ x) {
    __shared__ float tile[32][33];
    int b  = blockIdx.z;
    int l0 = blockIdx.x * 32;
    int d0 = blockIdx.y * 32;
    int tx = threadIdx.x, ty = threadIdx.y;
    #pragma unroll
    for (int i = 0; i < 32; i += 8)
        tile[ty+i][tx] = x[((size_t)(b*DIMc + d0+ty+i))*Lc + l0 + tx];
    __syncthreads();
    #pragma unroll
    for (int i = 0; i < 32; i += 8)
        g_xs[((size_t)b*Lc + l0+ty+i)*DIMc + d0+tx] = tile[tx][ty+i];
}

// ---------------- transpose out: xs (B,L,DIM) -> out (B,DIM,L) ----------------
__global__ void k_transpose_out(float* __restrict__ out) {
    __shared__ float tile[32][33];
    int b  = blockIdx.z;
    int l0 = blockIdx.x * 32;
    int d0 = blockIdx.y * 32;
    int tx = threadIdx.x, ty = threadIdx.y;
    #pragma unroll
    for (int i = 0; i < 32; i += 8)
        tile[ty+i][tx] = g_xs[((size_t)b*Lc + l0+ty+i)*DIMc + d0+tx];
    __syncthreads();
    #pragma unroll
    for (int i = 0; i < 32; i += 8)
        out[((size_t)(b*DIMc + d0+ty+i))*Lc + l0 + tx] = tile[tx][ty+i];
}

// ---------------- block reduction (128 threads) ----------------
__device__ __forceinline__ float block_sum128(float v, float* red) {
    #pragma unroll
    for (int o = 16; o > 0; o >>= 1) v += __shfl_xor_sync(0xffffffffu, v, o);
    int w = threadIdx.x >> 5;
    if ((threadIdx.x & 31) == 0) red[w] = v;
    __syncthreads();
    return red[0] + red[1] + red[2] + red[3];
}

// ---------------- rms norm (row = token) ----------------
template<int WHICH>  // 0: g_xs -> g_xn, 1: g_xs2 -> g_xn
__global__ void k_rms(const float* __restrict__ scale) {
    const float* in = (WHICH == 0) ? g_xs : g_xs2;
    int row = blockIdx.x;
    int tid = threadIdx.x;
    __shared__ float red[4];
    const float* p = in + (size_t)row * DIMc;
    float v0 = p[tid], v1 = p[tid+128], v2 = p[tid+256];
    float ss = block_sum128(v0*v0 + v1*v1 + v2*v2, red);
    float r = rsqrtf(ss * (1.0f/DIMc) + EPSc);
    float* o = g_xn + (size_t)row * DIMc;
    o[tid]     = v0 * r * scale[tid];
    o[tid+128] = v1 * r * scale[tid+128];
    o[tid+256] = v2 * r * scale[tid+256];
}

// ---------------- q/k rms + rope (in place on g_qkv) ----------------
__global__ void k_qkprep(const float* __restrict__ cosb, const float* __restrict__ sinb,
                         const float* __restrict__ nq, const float* __restrict__ nk) {
    int row = blockIdx.x;            // token in [0, BL)
    int l   = row & (Lc - 1);        // position within batch
    int tid = threadIdx.x;           // 128
    __shared__ float sbuf[DIMc];
    __shared__ float red[4];
    float* base = g_qkv + (size_t)row * (3*DIMc);
    #pragma unroll
    for (int part = 0; part < 2; part++) {
        float* p = base + part*DIMc;
        const float* sc = part ? nk : nq;
        float v0 = p[tid], v1 = p[tid+128], v2 = p[tid+256];
        float ss = block_sum128(v0*v0 + v1*v1 + v2*v2, red);
        float r = rsqrtf(ss * (1.0f/DIMc) + EPSc);
        sbuf[tid]     = v0 * r * sc[tid];
        sbuf[tid+128] = v1 * r * sc[tid+128];
        sbuf[tid+256] = v2 * r * sc[tid+256];
        __syncthreads();
        #pragma unroll
        for (int i = 0; i < 3; i++) {
            int d  = tid + i*128;
            int hd = d & 31;
            int pi = hd >> 1;
            float c = cosb[l*16 + pi], s = sinb[l*16 + pi];
            if (hd & 1) { float x0 = sbuf[d-1], x1 = sbuf[d];   p[d] = x0*s + x1*c; }
            else        { float x0 = sbuf[d],   x1 = sbuf[d+1]; p[d] = x0*c - x1*s; }
        }
        __syncthreads();
    }
}

// ---------------- attention (flash-style, one block = (batch-block, head)) ----------------
template<int VAR>
__device__ __forceinline__ void map_nb(int nb, int s, int& b, int& l) {
    if (VAR == 0)      { b = nb >> 7; int t = nb & 127; l = t*FRc + s; }
    else if (VAR == 1) { b = nb >> 6; int fr = nb & 63; l = s*FRc + fr; }
    else { b = nb >> 8; int rem = nb & 255; int t1 = rem >> 3; int f1 = rem & 7;
           int t2 = s >> 3; int f2 = s & 7; l = (t1*T2c + t2)*FRc + f1*F2c + f2; }
}

template<int VAR, int S, bool FIRST>
__global__ void k_attn() {
    __shared__ float Ks[S][HDc];
    __shared__ float Vs[S][HDc];
    int nb = blockIdx.x, h = blockIdx.y;
    int tid = threadIdx.x;   // blockDim.x == S
    // cooperative K/V load
    for (int idx = tid; idx < S*HDc; idx += S) {
        int s = idx >> 5, d = idx & 31;
        int b, l; map_nb<VAR>(nb, s, b, l);
        size_t base = ((size_t)(b*Lc + l))*(3*DIMc) + h*HDc + d;
        Ks[s][d] = g_qkv[base + DIMc];
        Vs[s][d] = g_qkv[base + 2*DIMc];
    }
    __syncthreads();
    int b, lq; map_nb<VAR>(nb, tid, b, lq);
    float q[HDc];
    {
        const float4* qp = (const float4*)(g_qkv + ((size_t)(b*Lc + lq))*(3*DIMc) + h*HDc);
        #pragma unroll
        for (int j = 0; j < 8; j++) { float4 v = qp[j]; q[4*j]=v.x; q[4*j+1]=v.y; q[4*j+2]=v.z; q[4*j+3]=v.w; }
    }
    float m = -1e30f, lsum = 0.0f, acc[HDc];
    #pragma unroll
    for (int d = 0; d < HDc; d++) acc[d] = 0.0f;
    const float scale = 0.17677669529663687f;  // 1/sqrt(32)
    for (int t = 0; t < S; t++) {
        float sc = 0.0f;
        #pragma unroll
        for (int d = 0; d < HDc; d++) sc = fmaf(q[d], Ks[t][d], sc);
        sc *= scale;
        if (sc > m) {
            float r = __expf(m - sc);
            lsum *= r;
            #pragma unroll
            for (int d = 0; d < HDc; d++) acc[d] *= r;
            m = sc;
        }
        float p = __expf(sc - m);
        lsum += p;
        #pragma unroll
        for (int d = 0; d < HDc; d++) acc[d] = fmaf(p, Vs[t][d], acc[d]);
    }
    float inv = 1.0f / lsum;
    float4* yo = (float4*)(g_y + ((size_t)(b*Lc + lq))*DIMc + h*HDc);
    #pragma unroll
    for (int j = 0; j < 8; j++) {
        float4 v; v.x = acc[4*j]*inv; v.y = acc[4*j+1]*inv; v.z = acc[4*j+2]*inv; v.w = acc[4*j+3]*inv;
        if (FIRST) yo[j] = v;
        else { float4 o = yo[j]; o.x += v.x; o.y += v.y; o.z += v.z; o.w += v.w; yo[j] = o; }
    }
}

// ---------------- SGEMM 128x128x8, 8x8 micro-tile, double-buffered, fma.rn.f32x2 ----------------
// ID 0: g_xn @ qkv_w  + qkv_b                  -> g_qkv   (K=384,  N=1152)
// ID 1: g_y  @ proj_w + proj_b + g_xs          -> g_xs2   (K=384,  N=384)
// ID 2: gelu(g_xn @ w1 + b1)                   -> g_h     (K=384,  N=1536)
// ID 3: g_h  @ w2 + b2 + g_xs2                 -> g_xs    (K=1536, N=384)
template<int ID>
__global__ void __launch_bounds__(256, 2) k_gemm(const float* __restrict__ W,
                                                 const float* __restrict__ bias) {
    constexpr int K = (ID == 3) ? 1536 : 384;
    constexpr int N = (ID == 0) ? 1152 : (ID == 2) ? 1536 : 384;
    const float* A   = (ID == 1) ? g_y : (ID == 3) ? g_h : g_xn;
    float*       C   = (ID == 0) ? g_qkv : (ID == 1) ? g_xs2 : (ID == 2) ? g_h : g_xs;
    const float* res = (ID == 1) ? g_xs : (ID == 3) ? g_xs2 : nullptr;

    __shared__ float As[2][8][128];
    __shared__ float Bs[2][8][128];
    int tid = threadIdx.x;
    int bm = blockIdx.y * 128;
    int bn = blockIdx.x * 128;
    int arow = tid >> 1,  acol = (tid & 1) * 4;
    int brow = tid >> 5,  bcol = (tid & 31) * 4;
    int tx = tid & 15,    ty = tid >> 4;

    // packed accumulators: acc2[i][j2] = (C[i][2*j2], C[i][2*j2+1]) as two fp32 lanes
    unsigned long long acc2[8][4];
    #pragma unroll
    for (int i = 0; i < 8; i++)
        #pragma unroll
        for (int j = 0; j < 4; j++) acc2[i][j] = 0ull;

    const float* Aptr = A + (size_t)(bm + arow)*K + acol;
    const float* Wptr = W + (size_t)brow*N + bn + bcol;

    // prologue: tile 0 -> buffer 0
    {
        float4 av = *(const float4*)(Aptr);
        As[0][acol+0][arow] = av.x; As[0][acol+1][arow] = av.y;
        As[0][acol+2][arow] = av.z; As[0][acol+3][arow] = av.w;
        float4 bv = *(const float4*)(Wptr);
        *(float4*)&Bs[0][brow][bcol] = bv;
    }
    __syncthreads();

    int buf = 0;
    #pragma unroll 1
    for (int k0 = 0; k0 < K; k0 += 8) {
        // prefetch next tile into registers (overlaps with compute below)
        float4 av_n, bv_n;
        const bool has_next = (k0 + 8 < K);
        if (has_next) {
            av_n = *(const float4*)(Aptr + k0 + 8);
            bv_n = *(const float4*)(Wptr + (size_t)(k0 + 8)*N);
        }
        // compute current tile (packed dual-FMA)
        #pragma unroll
        for (int kk = 0; kk < 8; kk++) {
            unsigned long long a2[8], b2[4];
            #pragma unroll
            for (int i = 0; i < 8; i++) {
                unsigned int ai = __float_as_uint(As[buf][kk][ty*8 + i]);
                asm("mov.b64 %0, {%1, %1};" : "=l"(a2[i]) : "r"(ai));
            }
            #pragma unroll
            for (int j = 0; j < 4; j++)  // 8-byte aligned LDS.64
                b2[j] = *(const unsigned long long*)&Bs[buf][kk][tx*8 + 2*j];
            #pragma unroll
            for (int i = 0; i < 8; i++)
                #pragma unroll
                for (int j = 0; j < 4; j++)
                    asm("fma.rn.f32x2 %0, %1, %2, %0;"
                        : "+l"(acc2[i][j]) : "l"(a2[i]), "l"(b2[j]));
        }
        // stage next tile into the other buffer
        if (has_next) {
            int nb = buf ^ 1;
            As[nb][acol+0][arow] = av_n.x; As[nb][acol+1][arow] = av_n.y;
            As[nb][acol+2][arow] = av_n.z; As[nb][acol+3][arow] = av_n.w;
            *(float4*)&Bs[nb][brow][bcol] = bv_n;
            __syncthreads();
            buf = nb;
        }
    }

    #pragma unroll
    for (int i = 0; i < 8; i++) {
        int m = bm + ty*8 + i;
        // unpack row i
        float accf[8];
        #pragma unroll
        for (int j = 0; j < 4; j++) {
            unsigned int lo, hi;
            asm("mov.b64 {%0, %1}, %2;" : "=r"(lo), "=r"(hi) : "l"(acc2[i][j]));
            accf[2*j]   = __uint_as_float(lo);
            accf[2*j+1] = __uint_as_float(hi);
        }
        #pragma unroll
        for (int jj = 0; jj < 8; jj += 4) {
            int n = bn + tx*8 + jj;
            float4 v;
            float* pv = &v.x;
            #pragma unroll
            for (int u = 0; u < 4; u++) {
                float c = accf[jj+u] + bias[n+u];
                if (ID == 1 || ID == 3) c += res[(size_t)m*N + n + u];
                if (ID == 2) {
                    // gelu(tanh approx) == c * sigmoid(2*0.79788456*(c + 0.044715 c^3))
                    float z = 1.5957691216057308f * (c + 0.044715f * c * c * c);
                    c = c / (1.0f + __expf(-z));
                }
                pv[u] = c;
            }
            *(float4*)(C + (size_t)m*N + n) = v;
        }
    }
}

// ---------------- launch ----------------
extern "C" void kernel_launch(void* const* d_in, const int* in_sizes, int n_in,
                              void* d_out, int out_size) {
    const float* x      = (const float*)d_in[0];
    const float* cosb   = (const float*)d_in[1];
    const float* sinb   = (const float*)d_in[2];
    const float* qkv_w  = (const float*)d_in[3];
    const float* qkv_b  = (const float*)d_in[4];
    const float* nq_s   = (const float*)d_in[5];
    const float* nk_s   = (const float*)d_in[6];
    const float* proj_w = (const float*)d_in[7];
    const float* proj_b = (const float*)d_in[8];
    const float* n1_s   = (const float*)d_in[9];
    const float* n2_s   = (const float*)d_in[10];
    const float* w1     = (const float*)d_in[11];
    const float* b1     = (const float*)d_in[12];
    const float* w2     = (const float*)d_in[13];
    const float* b2     = (const float*)d_in[14];
    float* out = (float*)d_out;

    dim3 tb(32, 8);
    k_transpose_in<<<dim3(Lc/32, DIMc/32, Bc), tb>>>(x);
    k_rms<0><<<BLc, 128>>>(n1_s);
    k_gemm<0><<<dim3(1152/128, BLc/128), 256>>>(qkv_w, qkv_b);
    k_qkprep<<<BLc, 128>>>(cosb, sinb, nq_s, nk_s);
    k_attn<0, FRc, true ><<<dim3(Bc*Tc,        NHc), FRc     >>>();   // time-block attn (S=64)
    k_attn<1, Tc,  false><<<dim3(Bc*FRc,       NHc), Tc      >>>();   // freq-block attn (S=128)
    k_attn<2, T2c*F2c, false><<<dim3(Bc*T1c*F1c, NHc), T2c*F2c>>>();  // tile attn (S=32)
    k_gemm<1><<<dim3(384/128, BLc/128), 256>>>(proj_w, proj_b);
    k_rms<1><<<BLc, 128>>>(n2_s);
    k_gemm<2><<<dim3(1536/128, BLc/128), 256>>>(w1, b1);
    k_gemm<3><<<dim3(384/128, BLc/128), 256>>>(w2, b2);
    k_transpose_out<<<dim3(Lc/32, DIMc/32, Bc), tb>>>(out);
}

// round 9
// speedup vs baseline: 1.3809x; 1.3809x over previous
#include <cuda_runtime.h>
#include <cuda_bf16.h>
#include <math.h>
#include <stdint.h>

// ---------------- problem constants ----------------
#define DIMc   384
#define NHc    12
#define HDc    32
#define Bc     4
#define Tc     128
#define FRc    64
#define Lc     (Tc*FRc)        // 8192
#define BLc    (Bc*Lc)         // 32768
#define T2c    4
#define F2c    8
#define T1c    (Tc/T2c)        // 32
#define F1c    (FRc/F2c)       // 8
#define EPSc   1e-6f

// ---------------- scratch (device globals; no runtime alloc) ----------------
__device__ float g_xs [BLc*DIMc];     // token-major activations (residual stream)
__device__ float g_xn [BLc*DIMc];     // rms-normalized activations
__device__ float g_qkv[BLc*3*DIMc];   // qkv (q,k roped in place)
__device__ float g_y  [BLc*DIMc];     // attention output accumulator
__device__ float g_xs2[BLc*DIMc];     // after proj residual
__device__ float g_h  [BLc*4*DIMc];   // mlp hidden
// transposed+split weights: [N][K] row-major, bf16 hi/lo
// offsets: qkv 0 (1152x384), proj 442368 (384x384), w1 589824 (1536x384), w2 1179648 (384x1536)
#define WT_TOT 1769472
__device__ __nv_bfloat16 g_wbf_hi[WT_TOT];
__device__ __nv_bfloat16 g_wbf_lo[WT_TOT];

// ---------------- helpers ----------------
__device__ __forceinline__ uint32_t smem_u32(const void* p) {
    uint32_t a;
    asm("{ .reg .u64 t; cvta.to.shared.u64 t, %1; cvt.u32.u64 %0, t; }" : "=r"(a) : "l"(p));
    return a;
}
#define SWZ128(o) ((o) ^ ((((uint32_t)(o)) >> 3) & 0x70u))

__device__ __forceinline__ void mma_bf16(float* d, const uint32_t* a, uint32_t b0, uint32_t b1) {
    asm volatile("mma.sync.aligned.m16n8k16.row.col.f32.bf16.bf16.f32 "
        "{%0,%1,%2,%3}, {%4,%5,%6,%7}, {%8,%9}, {%0,%1,%2,%3};"
        : "+f"(d[0]), "+f"(d[1]), "+f"(d[2]), "+f"(d[3])
        : "r"(a[0]), "r"(a[1]), "r"(a[2]), "r"(a[3]), "r"(b0), "r"(b1));
}
__device__ __forceinline__ void ldsm4(uint32_t* r, uint32_t addr) {
    asm volatile("ldmatrix.sync.aligned.m8n8.x4.shared.b16 {%0,%1,%2,%3}, [%4];"
        : "=r"(r[0]), "=r"(r[1]), "=r"(r[2]), "=r"(r[3]) : "r"(addr));
}
__device__ __forceinline__ void cpa16(uint32_t dst, const void* src) {
    asm volatile("cp.async.cg.shared.global [%0], [%1], 16;" :: "r"(dst), "l"(src) : "memory");
}
__device__ __forceinline__ uint32_t pack2(__nv_bfloat16 lo, __nv_bfloat16 hi) {
    return (uint32_t)__bfloat16_as_ushort(lo) | ((uint32_t)__bfloat16_as_ushort(hi) << 16);
}

// ---------------- weight transpose + bf16 split: W[K][N] -> [N][K] hi/lo ----------------
__global__ void k_wsplit(const float* __restrict__ W, int off, int K, int N) {
    __shared__ float t[32][33];
    int k0 = blockIdx.y * 32, n0 = blockIdx.x * 32;
    int tx = threadIdx.x, ty = threadIdx.y;
    #pragma unroll
    for (int i = 0; i < 32; i += 8)
        t[ty+i][tx] = W[(size_t)(k0+ty+i)*N + n0 + tx];
    __syncthreads();
    #pragma unroll
    for (int i = 0; i < 32; i += 8) {
        float v = t[tx][ty+i];
        __nv_bfloat16 h = __float2bfloat16(v);
        float hf = __bfloat162float(h);
        size_t o = (size_t)off + (size_t)(n0+ty+i)*K + k0 + tx;
        g_wbf_hi[o] = h;
        g_wbf_lo[o] = __float2bfloat16(v - hf);
    }
}

// ---------------- transpose in: x (B,DIM,L) -> xs (B,L,DIM) ----------------
__global__ void k_transpose_in(const float* __restrict__ x) {
    __shared__ float tile[32][33];
    int b  = blockIdx.z;
    int l0 = blockIdx.x * 32;
    int d0 = blockIdx.y * 32;
    int tx = threadIdx.x, ty = threadIdx.y;
    #pragma unroll
    for (int i = 0; i < 32; i += 8)
        tile[ty+i][tx] = x[((size_t)(b*DIMc + d0+ty+i))*Lc + l0 + tx];
    __syncthreads();
    #pragma unroll
    for (int i = 0; i < 32; i += 8)
        g_xs[((size_t)b*Lc + l0+ty+i)*DIMc + d0+tx] = tile[tx][ty+i];
}

// ---------------- transpose out: xs (B,L,DIM) -> out (B,DIM,L) ----------------
__global__ void k_transpose_out(float* __restrict__ out) {
    __shared__ float tile[32][33];
    int b  = blockIdx.z;
    int l0 = blockIdx.x * 32;
    int d0 = blockIdx.y * 32;
    int tx = threadIdx.x, ty = threadIdx.y;
    #pragma unroll
    for (int i = 0; i < 32; i += 8)
        tile[ty+i][tx] = g_xs[((size_t)b*Lc + l0+ty+i)*DIMc + d0+tx];
    __syncthreads();
    #pragma unroll
    for (int i = 0; i < 32; i += 8)
        out[((size_t)(b*DIMc + d0+ty+i))*Lc + l0 + tx] = tile[tx][ty+i];
}

// ---------------- block reduction (128 threads) ----------------
__device__ __forceinline__ float block_sum128(float v, float* red) {
    #pragma unroll
    for (int o = 16; o > 0; o >>= 1) v += __shfl_xor_sync(0xffffffffu, v, o);
    int w = threadIdx.x >> 5;
    if ((threadIdx.x & 31) == 0) red[w] = v;
    __syncthreads();
    return red[0] + red[1] + red[2] + red[3];
}

// ---------------- rms norm (row = token) ----------------
template<int WHICH>  // 0: g_xs -> g_xn, 1: g_xs2 -> g_xn
__global__ void k_rms(const float* __restrict__ scale) {
    const float* in = (WHICH == 0) ? g_xs : g_xs2;
    int row = blockIdx.x;
    int tid = threadIdx.x;
    __shared__ float red[4];
    const float* p = in + (size_t)row * DIMc;
    float v0 = p[tid], v1 = p[tid+128], v2 = p[tid+256];
    float ss = block_sum128(v0*v0 + v1*v1 + v2*v2, red);
    float r = rsqrtf(ss * (1.0f/DIMc) + EPSc);
    float* o = g_xn + (size_t)row * DIMc;
    o[tid]     = v0 * r * scale[tid];
    o[tid+128] = v1 * r * scale[tid+128];
    o[tid+256] = v2 * r * scale[tid+256];
}

// ---------------- q/k rms + rope (in place on g_qkv) ----------------
__global__ void k_qkprep(const float* __restrict__ cosb, const float* __restrict__ sinb,
                         const float* __restrict__ nq, const float* __restrict__ nk) {
    int row = blockIdx.x;            // token in [0, BL)
    int l   = row & (Lc - 1);        // position within batch
    int tid = threadIdx.x;           // 128
    __shared__ float sbuf[DIMc];
    __shared__ float red[4];
    float* base = g_qkv + (size_t)row * (3*DIMc);
    #pragma unroll
    for (int part = 0; part < 2; part++) {
        float* p = base + part*DIMc;
        const float* sc = part ? nk : nq;
        float v0 = p[tid], v1 = p[tid+128], v2 = p[tid+256];
        float ss = block_sum128(v0*v0 + v1*v1 + v2*v2, red);
        float r = rsqrtf(ss * (1.0f/DIMc) + EPSc);
        sbuf[tid]     = v0 * r * sc[tid];
        sbuf[tid+128] = v1 * r * sc[tid+128];
        sbuf[tid+256] = v2 * r * sc[tid+256];
        __syncthreads();
        #pragma unroll
        for (int i = 0; i < 3; i++) {
            int d  = tid + i*128;
            int hd = d & 31;
            int pi = hd >> 1;
            float c = cosb[l*16 + pi], s = sinb[l*16 + pi];
            if (hd & 1) { float x0 = sbuf[d-1], x1 = sbuf[d];   p[d] = x0*s + x1*c; }
            else        { float x0 = sbuf[d],   x1 = sbuf[d+1]; p[d] = x0*c - x1*s; }
        }
        __syncthreads();
    }
}

// ---------------- attention (flash-style, one block = (batch-block, head)) ----------------
template<int VAR>
__device__ __forceinline__ void map_nb(int nb, int s, int& b, int& l) {
    if (VAR == 0)      { b = nb >> 7; int t = nb & 127; l = t*FRc + s; }
    else if (VAR == 1) { b = nb >> 6; int fr = nb & 63; l = s*FRc + fr; }
    else { b = nb >> 8; int rem = nb & 255; int t1 = rem >> 3; int f1 = rem & 7;
           int t2 = s >> 3; int f2 = s & 7; l = (t1*T2c + t2)*FRc + f1*F2c + f2; }
}

template<int VAR, int S, bool FIRST>
__global__ void k_attn() {
    __shared__ float Ks[S][HDc];
    __shared__ float Vs[S][HDc];
    int nb = blockIdx.x, h = blockIdx.y;
    int tid = threadIdx.x;   // blockDim.x == S
    for (int idx = tid; idx < S*HDc; idx += S) {
        int s = idx >> 5, d = idx & 31;
        int b, l; map_nb<VAR>(nb, s, b, l);
        size_t base = ((size_t)(b*Lc + l))*(3*DIMc) + h*HDc + d;
        Ks[s][d] = g_qkv[base + DIMc];
        Vs[s][d] = g_qkv[base + 2*DIMc];
    }
    __syncthreads();
    int b, lq; map_nb<VAR>(nb, tid, b, lq);
    float q[HDc];
    {
        const float4* qp = (const float4*)(g_qkv + ((size_t)(b*Lc + lq))*(3*DIMc) + h*HDc);
        #pragma unroll
        for (int j = 0; j < 8; j++) { float4 v = qp[j]; q[4*j]=v.x; q[4*j+1]=v.y; q[4*j+2]=v.z; q[4*j+3]=v.w; }
    }
    float m = -1e30f, lsum = 0.0f, acc[HDc];
    #pragma unroll
    for (int d = 0; d < HDc; d++) acc[d] = 0.0f;
    const float scale = 0.17677669529663687f;  // 1/sqrt(32)
    for (int t = 0; t < S; t++) {
        float sc = 0.0f;
        #pragma unroll
        for (int d = 0; d < HDc; d++) sc = fmaf(q[d], Ks[t][d], sc);
        sc *= scale;
        if (sc > m) {
            float r = __expf(m - sc);
            lsum *= r;
            #pragma unroll
            for (int d = 0; d < HDc; d++) acc[d] *= r;
            m = sc;
        }
        float p = __expf(sc - m);
        lsum += p;
        #pragma unroll
        for (int d = 0; d < HDc; d++) acc[d] = fmaf(p, Vs[t][d], acc[d]);
    }
    float inv = 1.0f / lsum;
    float4* yo = (float4*)(g_y + ((size_t)(b*Lc + lq))*DIMc + h*HDc);
    #pragma unroll
    for (int j = 0; j < 8; j++) {
        float4 v; v.x = acc[4*j]*inv; v.y = acc[4*j+1]*inv; v.z = acc[4*j+2]*inv; v.w = acc[4*j+3]*inv;
        if (FIRST) yo[j] = v;
        else { float4 o = yo[j]; o.x += v.x; o.y += v.y; o.z += v.z; o.w += v.w; yo[j] = o; }
    }
}

// ---------------- mma.sync bf16-split GEMM, 128x128 CTA tile, K-chunks of 64 ----------------
// ID 0: g_xn @ qkv_w  + qkv_b                  -> g_qkv   (K=384,  N=1152)
// ID 1: g_y  @ proj_w + proj_b + g_xs          -> g_xs2   (K=384,  N=384)
// ID 2: gelu(g_xn @ w1 + b1)                   -> g_h     (K=384,  N=1536)
// ID 3: g_h  @ w2 + b2 + g_xs2                 -> g_xs    (K=1536, N=384)
// smem per buffer: Ahi(16K) Alo(16K) Bhi(16K) Blo(16K) = 64KB; 2 buffers = 128KB
#define TB_A_HI 0
#define TB_A_LO 16384
#define TB_B_HI 32768
#define TB_B_LO 49152
#define TB_STR  65536
#define MG_SMEM (2*TB_STR)

template<int ID>
__global__ void __launch_bounds__(256) k_mgemm(const float* __restrict__ bias) {
    constexpr int K   = (ID == 3) ? 1536 : 384;
    constexpr int N   = (ID == 0) ? 1152 : (ID == 2) ? 1536 : 384;
    constexpr int NCH = K / 64;
    const float* Act = (ID == 1) ? g_y : (ID == 3) ? g_h : g_xn;
    float*       C   = (ID == 0) ? g_qkv : (ID == 1) ? g_xs2 : (ID == 2) ? g_h : g_xs;
    const float* res = (ID == 1) ? g_xs : (ID == 3) ? g_xs2 : nullptr;
    constexpr size_t WOFF = (ID == 0) ? 0ull : (ID == 1) ? 442368ull : (ID == 2) ? 589824ull : 1179648ull;

    extern __shared__ char smem[];
    uint32_t sb = smem_u32(smem);
    int tid = threadIdx.x, lane = tid & 31, wid = tid >> 5;
    int bm = blockIdx.y * 128, bn = blockIdx.x * 128;
    const __nv_bfloat16* Wh = g_wbf_hi + WOFF;
    const __nv_bfloat16* Wl = g_wbf_lo + WOFF;

    // A staging: thread -> (row, k-half of 32)
    int arow = tid >> 1, akh = (tid & 1) * 32;
    const float* aP = Act + (size_t)(bm + arow)*K + akh;
    uint32_t a_sts[4];
    #pragma unroll
    for (int j = 0; j < 4; j++) a_sts[j] = SWZ128((uint32_t)(arow*128 + akh*2 + j*16));

    // B staging: 4 slots of 16B per half per thread
    size_t  b_src[4];
    uint32_t b_dst[4];
    #pragma unroll
    for (int j = 0; j < 4; j++) {
        int s = tid + 256*j;
        int br = s >> 3, bc = s & 7;
        b_src[j] = (size_t)(bn + br)*K + bc*8;
        b_dst[j] = SWZ128((uint32_t)(br*128 + bc*16));
    }

    float acc[4][4][4];
    #pragma unroll
    for (int a = 0; a < 4; a++)
        #pragma unroll
        for (int b = 0; b < 4; b++)
            #pragma unroll
            for (int c = 0; c < 4; c++) acc[a][b][c] = 0.0f;

    int wm = (wid & 1) * 64, wn = (wid >> 1) * 32;

    // ---- stage helpers (inlined via lambdas) ----
    auto stageB = [&](int buf, int k0) {
        uint32_t dH = sb + buf*TB_STR + TB_B_HI;
        uint32_t dL = sb + buf*TB_STR + TB_B_LO;
        #pragma unroll
        for (int j = 0; j < 4; j++) {
            cpa16(dH + b_dst[j], Wh + b_src[j] + k0);
            cpa16(dL + b_dst[j], Wl + b_src[j] + k0);
        }
        asm volatile("cp.async.commit_group;" ::: "memory");
    };
    auto storeA = [&](int buf, const float4* av) {
        char* dH = smem + buf*TB_STR + TB_A_HI;
        char* dL = smem + buf*TB_STR + TB_A_LO;
        #pragma unroll
        for (int j = 0; j < 4; j++) {
            float f[8];
            f[0]=av[2*j].x; f[1]=av[2*j].y; f[2]=av[2*j].z; f[3]=av[2*j].w;
            f[4]=av[2*j+1].x; f[5]=av[2*j+1].y; f[6]=av[2*j+1].z; f[7]=av[2*j+1].w;
            uint4 hv, lv;
            uint32_t* hp = &hv.x; uint32_t* lp = &lv.x;
            #pragma unroll
            for (int e = 0; e < 4; e++) {
                __nv_bfloat16 h0 = __float2bfloat16(f[2*e]);
                __nv_bfloat16 h1 = __float2bfloat16(f[2*e+1]);
                __nv_bfloat16 l0 = __float2bfloat16(f[2*e]   - __bfloat162float(h0));
                __nv_bfloat16 l1 = __float2bfloat16(f[2*e+1] - __bfloat162float(h1));
                hp[e] = pack2(h0, h1);
                lp[e] = pack2(l0, l1);
            }
            *(uint4*)(dH + a_sts[j]) = hv;
            *(uint4*)(dL + a_sts[j]) = lv;
        }
    };
    auto compute = [&](int buf) {
        uint32_t base = sb + buf*TB_STR;
        #pragma unroll
        for (int ks = 0; ks < 4; ks++) {
            // B fragments: 2 groups of n16, hi+lo
            uint32_t bh[2][4], bl[2][4];
            #pragma unroll
            for (int g = 0; g < 2; g++) {
                uint32_t row = wn + g*16 + ((lane >> 3) & 1)*8 + (lane & 7);
                uint32_t off = SWZ128(row*128 + (ks*16 + (lane >> 4)*8)*2);
                ldsm4(bh[g], base + TB_B_HI + off);
                ldsm4(bl[g], base + TB_B_LO + off);
            }
            #pragma unroll
            for (int mt = 0; mt < 4; mt++) {
                uint32_t row = wm + mt*16 + (lane & 15);
                uint32_t off = SWZ128(row*128 + ks*32 + (lane >> 4)*16);
                uint32_t ah[4], al[4];
                ldsm4(ah, base + TB_A_HI + off);
                ldsm4(al, base + TB_A_LO + off);
                #pragma unroll
                for (int nt = 0; nt < 4; nt++) {
                    int g = nt >> 1, t = nt & 1;
                    mma_bf16(acc[mt][nt], ah, bh[g][t], bh[g][2+t]);   // hi*hi
                    mma_bf16(acc[mt][nt], ah, bl[g][t], bl[g][2+t]);   // hi*lo
                    mma_bf16(acc[mt][nt], al, bh[g][t], bh[g][2+t]);   // lo*hi
                }
            }
        }
    };

    // ---- prologue: chunk 0 ----
    stageB(0, 0);
    {
        float4 av[8];
        #pragma unroll
        for (int j = 0; j < 8; j++) av[j] = *(const float4*)(aP + j*4);
        storeA(0, av);
    }
    asm volatile("cp.async.wait_group 0;" ::: "memory");
    __syncthreads();

    int buf = 0;
    #pragma unroll 1
    for (int i = 0; i < NCH; i++) {
        float4 av[8];
        const bool nxt = (i + 1 < NCH);
        if (nxt) {
            stageB(buf ^ 1, (i+1)*64);
            #pragma unroll
            for (int j = 0; j < 8; j++) av[j] = *(const float4*)(aP + (i+1)*64 + j*4);
        }
        compute(buf);
        if (nxt) storeA(buf ^ 1, av);
        asm volatile("cp.async.wait_group 0;" ::: "memory");
        __syncthreads();
        buf ^= 1;
    }

    // ---- epilogue: fp32 accs in registers -> bias/residual/gelu -> C ----
    float bias2[4][2];
    #pragma unroll
    for (int nt = 0; nt < 4; nt++) {
        int n = bn + wn + nt*8 + (lane & 3)*2;
        bias2[nt][0] = bias[n];
        bias2[nt][1] = bias[n+1];
    }
    #pragma unroll
    for (int mt = 0; mt < 4; mt++) {
        #pragma unroll
        for (int h = 0; h < 2; h++) {
            int m = bm + wm + mt*16 + (lane >> 2) + h*8;
            float* crow = C + (size_t)m * N;
            const float* rrow = res ? (res + (size_t)m * N) : nullptr;
            #pragma unroll
            for (int nt = 0; nt < 4; nt++) {
                int n = bn + wn + nt*8 + (lane & 3)*2;
                float c0 = acc[mt][nt][h*2+0] + bias2[nt][0];
                float c1 = acc[mt][nt][h*2+1] + bias2[nt][1];
                if (ID == 1 || ID == 3) {
                    float2 rv = *(const float2*)(rrow + n);
                    c0 += rv.x; c1 += rv.y;
                }
                if (ID == 2) {
                    float z0 = 1.5957691216057308f * (c0 + 0.044715f * c0 * c0 * c0);
                    float z1 = 1.5957691216057308f * (c1 + 0.044715f * c1 * c1 * c1);
                    c0 = c0 / (1.0f + __expf(-z0));
                    c1 = c1 / (1.0f + __expf(-z1));
                }
                float2 v; v.x = c0; v.y = c1;
                *(float2*)(crow + n) = v;
            }
        }
    }
}

// ---------------- launch ----------------
extern "C" void kernel_launch(void* const* d_in, const int* in_sizes, int n_in,
                              void* d_out, int out_size) {
    const float* x      = (const float*)d_in[0];
    const float* cosb   = (const float*)d_in[1];
    const float* sinb   = (const float*)d_in[2];
    const float* qkv_w  = (const float*)d_in[3];
    const float* qkv_b  = (const float*)d_in[4];
    const float* nq_s   = (const float*)d_in[5];
    const float* nk_s   = (const float*)d_in[6];
    const float* proj_w = (const float*)d_in[7];
    const float* proj_b = (const float*)d_in[8];
    const float* n1_s   = (const float*)d_in[9];
    const float* n2_s   = (const float*)d_in[10];
    const float* w1     = (const float*)d_in[11];
    const float* b1     = (const float*)d_in[12];
    const float* w2     = (const float*)d_in[13];
    const float* b2     = (const float*)d_in[14];
    float* out = (float*)d_out;

    cudaFuncSetAttribute(k_mgemm<0>, cudaFuncAttributeMaxDynamicSharedMemorySize, MG_SMEM);
    cudaFuncSetAttribute(k_mgemm<1>, cudaFuncAttributeMaxDynamicSharedMemorySize, MG_SMEM);
    cudaFuncSetAttribute(k_mgemm<2>, cudaFuncAttributeMaxDynamicSharedMemorySize, MG_SMEM);
    cudaFuncSetAttribute(k_mgemm<3>, cudaFuncAttributeMaxDynamicSharedMemorySize, MG_SMEM);

    dim3 tb(32, 8);
    // weight transpose+split (independent of activations)
    k_wsplit<<<dim3(1152/32, 384/32),  tb>>>(qkv_w,  0,       384,  1152);
    k_wsplit<<<dim3(384/32,  384/32),  tb>>>(proj_w, 442368,  384,  384);
    k_wsplit<<<dim3(1536/32, 384/32),  tb>>>(w1,     589824,  384,  1536);
    k_wsplit<<<dim3(384/32,  1536/32), tb>>>(w2,     1179648, 1536, 384);

    k_transpose_in<<<dim3(Lc/32, DIMc/32, Bc), tb>>>(x);
    k_rms<0><<<BLc, 128>>>(n1_s);
    k_mgemm<0><<<dim3(1152/128, BLc/128), 256, MG_SMEM>>>(qkv_b);
    k_qkprep<<<BLc, 128>>>(cosb, sinb, nq_s, nk_s);
    k_attn<0, FRc, true ><<<dim3(Bc*Tc,        NHc), FRc     >>>();   // time-block attn (S=64)
    k_attn<1, Tc,  false><<<dim3(Bc*FRc,       NHc), Tc      >>>();   // freq-block attn (S=128)
    k_attn<2, T2c*F2c, false><<<dim3(Bc*T1c*F1c, NHc), T2c*F2c>>>();  // tile attn (S=32)
    k_mgemm<1><<<dim3(384/128,  BLc/128), 256, MG_SMEM>>>(proj_b);
    k_rms<1><<<BLc, 128>>>(n2_s);
    k_mgemm<2><<<dim3(1536/128, BLc/128), 256, MG_SMEM>>>(b1);
    k_mgemm<3><<<dim3(384/128,  BLc/128), 256, MG_SMEM>>>(b2);
    k_transpose_out<<<dim3(Lc/32, DIMc/32, Bc), tb>>>(out);
}